// round 1
// baseline (speedup 1.0000x reference)
#include <cuda_runtime.h>
#include <math.h>

#define BSZ 64
#define TT  512
#define DD  768
#define WW  255
#define HH  8
#define DHD 96
#define BW  (BSZ*WW)      // 16320
#define DFF 3072

// ---------------- scratch (device globals; no allocation allowed) ----------
static __device__ float g_feat[BW*DD];
static __device__ float g_q[BW*DD];
static __device__ float g_k[BW*DD];
static __device__ float g_v[BW*DD];
static __device__ float g_ctx[BW*DD];
static __device__ float g_tmp[BW*DD];
static __device__ float g_x[BW*DD];
static __device__ float g_x2[BW*DD];
static __device__ float g_ff1[(long)BW*DFF];
static __device__ int   g_first[BW];

// ---------------- first-subtoken gather ------------------------------------
__global__ void init_first_k(int* first) {
    int i = blockIdx.x * blockDim.x + threadIdx.x;
    if (i < BW) first[i] = 0x7FFFFFFF;
}

__global__ void scan_first_k(const int* __restrict__ wi, int* __restrict__ first) {
    int i = blockIdx.x * blockDim.x + threadIdx.x;
    if (i < BSZ * TT) {
        int w = wi[i];
        if (w >= 0 && w < WW) atomicMin(&first[(i / TT) * WW + w], i % TT);
    }
}

__global__ void gather_k(const float* __restrict__ ob, const int* __restrict__ first,
                         float* __restrict__ feat) {
    int bw = blockIdx.x;
    int t = first[bw];
    if (t >= TT) t = 0;  // argmax(all false) == 0
    int b = bw / WW;
    const float4* src = (const float4*)(ob + ((long)(b * TT + t)) * DD);
    float4* dst = (float4*)(feat + (long)bw * DD);
    dst[threadIdx.x] = src[threadIdx.x];   // 192 threads * 4 = 768
}

// ---------------- SGEMM: C[M,N] = A[M,K] @ B[K,N] + bias, optional relu ----
#define BM 128
#define BN 128
#define BK 8

__global__ __launch_bounds__(256)
void sgemm_bias_k(const float* __restrict__ A, const float* __restrict__ B,
                  const float* __restrict__ bias, float* __restrict__ C,
                  int M, int N, int K, int relu) {
    __shared__ float As[BK][BM];
    __shared__ float Bs[BK][BN];
    int tid = threadIdx.x;
    int bm = blockIdx.y * BM, bn = blockIdx.x * BN;

    int arow = tid >> 1;            // 0..127
    int acol = (tid & 1) * 4;       // 0 or 4
    int brow = tid >> 5;            // 0..7
    int bcol = (tid & 31) * 4;      // 0..124

    int tx = tid & 15;              // col group
    int ty = tid >> 4;              // row group

    const float* Aptr = A + (long)(bm + arow) * K + acol;
    const float* Bptr = B + (long)brow * N + bn + bcol;
    bool arow_ok = (bm + arow) < M;

    float acc[8][8];
    #pragma unroll
    for (int i = 0; i < 8; i++)
        #pragma unroll
        for (int j = 0; j < 8; j++) acc[i][j] = 0.f;

    for (int k0 = 0; k0 < K; k0 += BK) {
        float4 av = arow_ok ? *(const float4*)Aptr : make_float4(0.f, 0.f, 0.f, 0.f);
        float4 bv = *(const float4*)Bptr;
        As[acol + 0][arow] = av.x;
        As[acol + 1][arow] = av.y;
        As[acol + 2][arow] = av.z;
        As[acol + 3][arow] = av.w;
        *(float4*)&Bs[brow][bcol] = bv;
        __syncthreads();
        #pragma unroll
        for (int kk = 0; kk < BK; kk++) {
            float4 a0 = *(const float4*)&As[kk][ty * 4];
            float4 a1 = *(const float4*)&As[kk][64 + ty * 4];
            float4 b0 = *(const float4*)&Bs[kk][tx * 4];
            float4 b1 = *(const float4*)&Bs[kk][64 + tx * 4];
            float ar[8] = {a0.x, a0.y, a0.z, a0.w, a1.x, a1.y, a1.z, a1.w};
            float br[8] = {b0.x, b0.y, b0.z, b0.w, b1.x, b1.y, b1.z, b1.w};
            #pragma unroll
            for (int i = 0; i < 8; i++)
                #pragma unroll
                for (int j = 0; j < 8; j++) acc[i][j] += ar[i] * br[j];
        }
        __syncthreads();
        Aptr += BK;
        Bptr += (long)BK * N;
    }

    #pragma unroll
    for (int i = 0; i < 8; i++) {
        int row = bm + ((i < 4) ? (ty * 4 + i) : (64 + ty * 4 + i - 4));
        if (row >= M) continue;
        #pragma unroll
        for (int jh = 0; jh < 2; jh++) {
            int col = bn + ((jh == 0) ? (tx * 4) : (64 + tx * 4));
            float4 o;
            float* a = &acc[i][jh * 4];
            o.x = a[0] + bias[col + 0];
            o.y = a[1] + bias[col + 1];
            o.z = a[2] + bias[col + 2];
            o.w = a[3] + bias[col + 3];
            if (relu) {
                o.x = fmaxf(o.x, 0.f); o.y = fmaxf(o.y, 0.f);
                o.z = fmaxf(o.z, 0.f); o.w = fmaxf(o.w, 0.f);
            }
            *(float4*)&C[(long)row * N + col] = o;
        }
    }
}

// ---------------- fused attention: one block per (b,h) ---------------------
#define KPAD 97
#define ATTN_SMEM ((2*WW*KPAD + 8*DHD + 8*256) * 4)

__global__ __launch_bounds__(256)
void attn_k(const float* __restrict__ q, const float* __restrict__ k,
            const float* __restrict__ v, float* __restrict__ ctx) {
    int b = blockIdx.x / HH, h = blockIdx.x % HH;
    extern __shared__ float sm[];
    float* ks = sm;                       // WW * KPAD
    float* vs = ks + WW * KPAD;           // WW * KPAD
    float* qs = vs + WW * KPAD;           // 8 * 96
    float* ps = qs + 8 * DHD;             // 8 * 256
    int tid = threadIdx.x, warp = tid >> 5, lane = tid & 31;

    for (int idx = tid; idx < WW * DHD; idx += 256) {
        int key = idx / DHD, d = idx % DHD;
        long g = ((long)(b * WW + key)) * DD + h * DHD + d;
        ks[key * KPAD + d] = k[g];
        vs[key * KPAD + d] = v[g];
    }
    __syncthreads();

    const float scale = 0.10206207261596575f;  // 1/sqrt(96)

    for (int row0 = 0; row0 < WW; row0 += 8) {
        int row = row0 + warp;
        if (row < WW) {
            for (int d = lane; d < DHD; d += 32)
                qs[warp * DHD + d] = q[((long)(b * WW + row)) * DD + h * DHD + d];
        }
        __syncwarp();
        if (row < WW) {
            float sc[8];
            float m = -1e30f;
            #pragma unroll
            for (int kk = 0; kk < 8; kk++) {
                int key = lane + kk * 32;
                float s = -1e30f;
                if (key < WW) {
                    s = 0.f;
                    #pragma unroll 8
                    for (int d = 0; d < DHD; d++)
                        s += qs[warp * DHD + d] * ks[key * KPAD + d];
                    s *= scale;
                }
                sc[kk] = s;
                m = fmaxf(m, s);
            }
            #pragma unroll
            for (int o = 16; o; o >>= 1) m = fmaxf(m, __shfl_xor_sync(0xffffffffu, m, o));
            float sum = 0.f;
            #pragma unroll
            for (int kk = 0; kk < 8; kk++) {
                float e = (sc[kk] > -1e29f) ? __expf(sc[kk] - m) : 0.f;
                sc[kk] = e; sum += e;
            }
            #pragma unroll
            for (int o = 16; o; o >>= 1) sum += __shfl_xor_sync(0xffffffffu, sum, o);
            float inv = 1.f / sum;
            #pragma unroll
            for (int kk = 0; kk < 8; kk++) {
                int key = lane + kk * 32;
                if (key < 256) ps[warp * 256 + key] = sc[kk] * inv;
            }
        }
        __syncwarp();
        if (row < WW) {
            int d0 = lane * 3;
            float a0 = 0.f, a1 = 0.f, a2 = 0.f;
            for (int key = 0; key < WW; key++) {
                float p = ps[warp * 256 + key];
                const float* vr = &vs[key * KPAD + d0];
                a0 += p * vr[0];
                a1 += p * vr[1];
                a2 += p * vr[2];
            }
            float* o = &ctx[((long)(b * WW + row)) * DD + h * DHD + d0];
            o[0] = a0; o[1] = a1; o[2] = a2;
        }
        __syncwarp();
    }
}

// ---------------- block reduce helper ---------------------------------------
__device__ __forceinline__ float block_reduce_sum(float val, float* red) {
    int lane = threadIdx.x & 31, warp = threadIdx.x >> 5;
    #pragma unroll
    for (int o = 16; o; o >>= 1) val += __shfl_xor_sync(0xffffffffu, val, o);
    if (lane == 0) red[warp] = val;
    __syncthreads();
    if (warp == 0) {
        float v = (lane < 8) ? red[lane] : 0.f;
        #pragma unroll
        for (int o = 4; o; o >>= 1) v += __shfl_xor_sync(0xffffffffu, v, o);
        if (lane == 0) red[0] = v;
    }
    __syncthreads();
    float r = red[0];
    __syncthreads();
    return r;
}

// ---------------- residual add + layernorm ----------------------------------
__global__ __launch_bounds__(256)
void add_ln_k(const float* __restrict__ X, const float* __restrict__ Y,
              const float* __restrict__ g, const float* __restrict__ bb,
              float* __restrict__ out) {
    __shared__ float red[32];
    int row = blockIdx.x, tid = threadIdx.x;
    const float* x = X + (long)row * DD;
    const float* y = Y + (long)row * DD;
    float v[3];
    float s = 0.f;
    #pragma unroll
    for (int i = 0; i < 3; i++) {
        int c = tid + 256 * i;
        v[i] = x[c] + y[c];
        s += v[i];
    }
    float mean = block_reduce_sum(s, red) * (1.f / DD);
    float vs = 0.f;
    #pragma unroll
    for (int i = 0; i < 3; i++) { float d = v[i] - mean; vs += d * d; }
    float var = block_reduce_sum(vs, red) * (1.f / DD);
    float rstd = rsqrtf(var + 1e-5f);
    float* o = out + (long)row * DD;
    #pragma unroll
    for (int i = 0; i < 3; i++) {
        int c = tid + 256 * i;
        o[c] = (v[i] - mean) * rstd * g[c] + bb[c];
    }
}

// ---------------- final: LN + linear(2) + softmax + argmax ------------------
__global__ __launch_bounds__(256)
void final_k(const float* __restrict__ X, const float* __restrict__ g,
             const float* __restrict__ bb, const float* __restrict__ lw,
             const float* __restrict__ lb, float* __restrict__ probs,
             float* __restrict__ path, int write_path) {
    __shared__ float red[32];
    int row = blockIdx.x, tid = threadIdx.x;
    const float* x = X + (long)row * DD;
    float v[3];
    float s = 0.f;
    #pragma unroll
    for (int i = 0; i < 3; i++) { v[i] = x[tid + 256 * i]; s += v[i]; }
    float mean = block_reduce_sum(s, red) * (1.f / DD);
    float vs = 0.f;
    #pragma unroll
    for (int i = 0; i < 3; i++) { float d = v[i] - mean; vs += d * d; }
    float var = block_reduce_sum(vs, red) * (1.f / DD);
    float rstd = rsqrtf(var + 1e-5f);
    float l0 = 0.f, l1 = 0.f;
    #pragma unroll
    for (int i = 0; i < 3; i++) {
        int c = tid + 256 * i;
        float yv = (v[i] - mean) * rstd * g[c] + bb[c];
        l0 += yv * lw[2 * c + 0];
        l1 += yv * lw[2 * c + 1];
    }
    l0 = block_reduce_sum(l0, red);
    l1 = block_reduce_sum(l1, red);
    if (tid == 0) {
        l0 += lb[0]; l1 += lb[1];
        float m = fmaxf(l0, l1);
        float e0 = expf(l0 - m), e1 = expf(l1 - m);
        float inv = 1.f / (e0 + e1);
        probs[2 * row + 0] = e0 * inv;
        probs[2 * row + 1] = e1 * inv;
        if (write_path) path[row] = (l1 > l0) ? 1.f : 0.f;
    }
}

// ---------------- launch -----------------------------------------------------
extern "C" void kernel_launch(void* const* d_in, const int* in_sizes, int n_in,
                              void* d_out, int out_size) {
    const float* ob  = (const float*)d_in[0];
    const int*   wi  = (const int*)d_in[1];
    const float* Wq  = (const float*)d_in[2];   const float* bq  = (const float*)d_in[3];
    const float* Wk  = (const float*)d_in[4];   const float* bk  = (const float*)d_in[5];
    const float* Wv  = (const float*)d_in[6];   const float* bv  = (const float*)d_in[7];
    const float* Wo  = (const float*)d_in[8];   const float* bo  = (const float*)d_in[9];
    const float* l1g = (const float*)d_in[10];  const float* l1b = (const float*)d_in[11];
    const float* W1f = (const float*)d_in[12];  const float* b1f = (const float*)d_in[13];
    const float* W2f = (const float*)d_in[14];  const float* b2f = (const float*)d_in[15];
    const float* l2g = (const float*)d_in[16];  const float* l2b = (const float*)d_in[17];
    const float* ng  = (const float*)d_in[18];  const float* nb  = (const float*)d_in[19];
    const float* lw  = (const float*)d_in[20];  const float* lb  = (const float*)d_in[21];

    float *feat, *q, *k, *v, *ctx, *tmp, *x, *x2, *ff1; int* first;
    cudaGetSymbolAddress((void**)&feat, g_feat);
    cudaGetSymbolAddress((void**)&q,    g_q);
    cudaGetSymbolAddress((void**)&k,    g_k);
    cudaGetSymbolAddress((void**)&v,    g_v);
    cudaGetSymbolAddress((void**)&ctx,  g_ctx);
    cudaGetSymbolAddress((void**)&tmp,  g_tmp);
    cudaGetSymbolAddress((void**)&x,    g_x);
    cudaGetSymbolAddress((void**)&x2,   g_x2);
    cudaGetSymbolAddress((void**)&ff1,  g_ff1);
    cudaGetSymbolAddress((void**)&first, g_first);

    cudaFuncSetAttribute(attn_k, cudaFuncAttributeMaxDynamicSharedMemorySize, ATTN_SMEM);

    // gather
    init_first_k<<<(BW + 255) / 256, 256>>>(first);
    scan_first_k<<<(BSZ * TT + 255) / 256, 256>>>(wi, first);
    gather_k<<<BW, 192>>>(ob, first, feat);

    // QKV projections
    dim3 g6(6, 128), g24(24, 128);
    sgemm_bias_k<<<g6, 256>>>(feat, Wq, bq, q, BW, DD, DD, 0);
    sgemm_bias_k<<<g6, 256>>>(feat, Wk, bk, k, BW, DD, DD, 0);
    sgemm_bias_k<<<g6, 256>>>(feat, Wv, bv, v, BW, DD, DD, 0);

    // attention
    attn_k<<<BSZ * HH, 256, ATTN_SMEM>>>(q, k, v, ctx);

    // output proj + LN1
    sgemm_bias_k<<<g6, 256>>>(ctx, Wo, bo, tmp, BW, DD, DD, 0);
    add_ln_k<<<BW, 256>>>(feat, tmp, l1g, l1b, x);

    // FFN + LN2
    sgemm_bias_k<<<g24, 256>>>(x, W1f, b1f, ff1, BW, DFF, DD, 1);
    sgemm_bias_k<<<g6, 256>>>(ff1, W2f, b2f, tmp, BW, DD, DFF, 0);
    add_ln_k<<<BW, 256>>>(x, tmp, l2g, l2b, x2);

    // final LN + linear + softmax + argmax
    float* probs = (float*)d_out;
    float* path  = probs + (long)BW * 2;
    int wp = (out_size >= BW * 3) ? 1 : 0;
    final_k<<<BW, 256>>>(x2, ng, nb, lw, lb, probs, path, wp);
}